// round 6
// baseline (speedup 1.0000x reference)
#include <cuda_runtime.h>
#include <math.h>

#define NU_ 200000
#define NI_ 100000
#define NG_ 50000
#define B_  65536
#define D_  256

typedef unsigned long long ull;

// Scratch (static device globals -- no allocation APIs).
__device__ __align__(16) float g_up[NU_ * 16];   // user attention partials
__device__ __align__(16) float g_ia[NI_ * 16];   // item attention partials
__device__ __align__(16) float g_ip[NI_ * 8];    // item prediction partials
__device__ __align__(16) float g_wab[4096];      // permuted pred-MLP weights

// packed f32x2 helpers
__device__ __forceinline__ ull splat2(float x) {
    ull r;
    asm("mov.b64 %0, {%1, %1};" : "=l"(r) : "f"(x));
    return r;
}
__device__ __forceinline__ void fma2(ull& acc, ull a, ull b) {
    asm("fma.rn.f32x2 %0, %1, %2, %0;" : "+l"(acc) : "l"(a), "l"(b));
}

// ---------------------------------------------------------------------------
// Fused precompute. Blocks [0,1172): one warp = one 32-row tile.
//   warps [0,6250): users (16 att outputs)     -> g_up
//   warps [6250,9375): items (16 att + 8 pred) -> g_ia, g_ip
// Block 1172: builds g_wab (permuted pred weights for agree_main).
// Inner product uses packed fma.rn.f32x2 over f-pairs: weight pair is a
// native 64-bit smem load, x is splat once per (row,d). Halves FFMA count.
// ---------------------------------------------------------------------------
__global__ __launch_bounds__(256) void pre_all(const float* __restrict__ ue,
                                               const float* __restrict__ ie,
                                               const float* __restrict__ aw1,
                                               const float* __restrict__ pw1) {
    if (blockIdx.x == 1172) {
        // g_wab[j*512 + (k*32+lane)*2 + {0,1}] = {pw1[d][j], pw1[256+d][j]}
        // with d = (k<4) ? lane*4+k : 128 + lane*4 + (k-4)
        for (int t = 0; t < 16; t++) {
            int idx = t * 256 + threadIdx.x;
            int j = idx >> 9;
            int w = (idx >> 1) & 255;
            int c = idx & 1;
            int k = w >> 5, lane = w & 31;
            int d = (k < 4) ? (lane * 4 + k) : (128 + lane * 4 + (k - 4));
            g_wab[idx] = c ? pw1[(256 + d) * 8 + j] : pw1[d * 8 + j];
        }
        return;
    }

    __shared__ __align__(16) float Wu[256 * 16];
    __shared__ __align__(16) float Wi[256 * 24];
    for (int idx = threadIdx.x; idx < 256 * 16; idx += 256) Wu[idx] = aw1[idx];
    for (int idx = threadIdx.x; idx < 256 * 24; idx += 256) {
        int d = idx / 24, f = idx % 24;
        Wi[idx] = (f < 16) ? aw1[(256 + d) * 16 + f]
                           : pw1[(512 + d) * 8 + (f - 16)];
    }
    __syncthreads();

    int w = blockIdx.x * 8 + (threadIdx.x >> 5);
    if (w >= 9375) return;
    int lane = threadIdx.x & 31;
    int ug = lane >> 2, fg = lane & 3;

    if (w < 6250) {
        // ---- user tile: 32 users x 16 f; lane: 4 users x 2 f-pairs ----
        int u0 = w * 32 + ug * 4;
        const float* r0 = ue + (size_t)u0 * D_;

        ull acc2[4][2];
#pragma unroll
        for (int i = 0; i < 4; i++) { acc2[i][0] = 0ull; acc2[i][1] = 0ull; }

        float4 x[4];
#pragma unroll
        for (int i = 0; i < 4; i++) x[i] = *(const float4*)(r0 + i * D_);

#pragma unroll 2
        for (int q = 0; q < 64; q++) {
            float4 xn[4];
            if (q < 63) {
#pragma unroll
                for (int i = 0; i < 4; i++)
                    xn[i] = *(const float4*)(r0 + i * D_ + (q + 1) * 4);
            }
#pragma unroll
            for (int dd = 0; dd < 4; dd++) {
                ulonglong2 bp =
                    *(const ulonglong2*)&Wu[(q * 4 + dd) * 16 + fg * 4];
#pragma unroll
                for (int i = 0; i < 4; i++) {
                    float xv = (dd == 0) ? x[i].x : (dd == 1) ? x[i].y
                              : (dd == 2) ? x[i].z : x[i].w;
                    ull xs = splat2(xv);
                    fma2(acc2[i][0], xs, bp.x);
                    fma2(acc2[i][1], xs, bp.y);
                }
            }
            if (q < 63) {
#pragma unroll
                for (int i = 0; i < 4; i++) x[i] = xn[i];
            }
        }
#pragma unroll
        for (int i = 0; i < 4; i++) {
            *(ull*)&g_up[(u0 + i) * 16 + fg * 4 + 0] = acc2[i][0];
            *(ull*)&g_up[(u0 + i) * 16 + fg * 4 + 2] = acc2[i][1];
        }
    } else {
        // ---- item tile: 32 items x 24 f; lane: 4 items x 3 f-pairs ----
        int t = w - 6250;
        int i0 = t * 32 + ug * 4;
        const float* r0 = ie + (size_t)i0 * D_;

        ull acc2[4][3];
#pragma unroll
        for (int i = 0; i < 4; i++)
#pragma unroll
            for (int p = 0; p < 3; p++) acc2[i][p] = 0ull;

        float4 x[4];
#pragma unroll
        for (int i = 0; i < 4; i++) x[i] = *(const float4*)(r0 + i * D_);

#pragma unroll 2
        for (int q = 0; q < 64; q++) {
            float4 xn[4];
            if (q < 63) {
#pragma unroll
                for (int i = 0; i < 4; i++)
                    xn[i] = *(const float4*)(r0 + i * D_ + (q + 1) * 4);
            }
#pragma unroll
            for (int dd = 0; dd < 4; dd++) {
                const float* wr = &Wi[(q * 4 + dd) * 24 + fg * 6];
                ull b0 = *(const ull*)(wr + 0);
                ull b1 = *(const ull*)(wr + 2);
                ull b2 = *(const ull*)(wr + 4);
#pragma unroll
                for (int i = 0; i < 4; i++) {
                    float xv = (dd == 0) ? x[i].x : (dd == 1) ? x[i].y
                              : (dd == 2) ? x[i].z : x[i].w;
                    ull xs = splat2(xv);
                    fma2(acc2[i][0], xs, b0);
                    fma2(acc2[i][1], xs, b1);
                    fma2(acc2[i][2], xs, b2);
                }
            }
            if (q < 63) {
#pragma unroll
                for (int i = 0; i < 4; i++) x[i] = xn[i];
            }
        }
#pragma unroll
        for (int i = 0; i < 4; i++)
#pragma unroll
            for (int p = 0; p < 3; p++) {
                int f = fg * 6 + 2 * p;      // even; pair never straddles f=16
                int it = i0 + i;
                if (f < 16) *(ull*)&g_ia[it * 16 + f] = acc2[i][p];
                else        *(ull*)&g_ip[it * 8 + (f - 16)] = acc2[i][p];
            }
    }
}

// ---------------------------------------------------------------------------
// Main kernel: one warp per batch element, 8 warps/block.
// Lane owns d in {lane*4+r} U {128+lane*4+r}: fully-coalesced LDG.128 rows.
// ALL loads (12 heavy rows + 5 attention-partial rows) issued before any
// dependent math so DRAM/L2 latency hides under the scalar section.
// ---------------------------------------------------------------------------
__global__ __launch_bounds__(256) void agree_main(
    const int*   __restrict__ gidx, const int*   __restrict__ iidx,
    const int*   __restrict__ gmem, const float* __restrict__ ue,
    const float* __restrict__ ie,   const float* __restrict__ ge,
    const float* __restrict__ ab1,  const float* __restrict__ aw2,
    const float* __restrict__ ab2,  const float* __restrict__ cw,
    const float* __restrict__ cb,   const float* __restrict__ pb1,
    const float* __restrict__ pw2,  const float* __restrict__ pb2,
    float* __restrict__ out) {
    __shared__ __align__(16) float Wab[4096];
    {
        const float4* s4 = (const float4*)g_wab;
        float4* d4 = (float4*)Wab;
#pragma unroll
        for (int i = 0; i < 4; i++)
            d4[threadIdx.x + i * 256] = s4[threadIdx.x + i * 256];
    }
    __syncthreads();

    int b = blockIdx.x * 8 + (threadIdx.x >> 5);
    int lane = threadIdx.x & 31;
    int f = lane & 15;

    int gid = gidx[b];
    int iid = iidx[b];
    int4 mv = ((const int4*)gmem)[gid];
    int m[4] = {mv.x, mv.y, mv.z, mv.w};

    // ---- issue every load up front ----
    const float* gr = ge + (size_t)gid * D_;
    const float* ir = ie + (size_t)iid * D_;
    float4 gA = *(const float4*)(gr + lane * 4);
    float4 gB = *(const float4*)(gr + 128 + lane * 4);
    float4 iA = *(const float4*)(ir + lane * 4);
    float4 iB = *(const float4*)(ir + 128 + lane * 4);
    float iav = g_ia[iid * 16 + f];
    float upv[4];
    float4 mA[4], mB[4];
#pragma unroll
    for (int s = 0; s < 4; s++) {
        const float* mr = ue + (size_t)m[s] * D_;
        mA[s] = *(const float4*)(mr + lane * 4);
        mB[s] = *(const float4*)(mr + 128 + lane * 4);
        upv[s] = g_up[m[s] * 16 + f];
    }

    // ---- attention logits from precomputed partials ----
    float base = iav + ab1[f];
    float w2v = aw2[f];
    float ab2v = ab2[0];
    float lg[4];
#pragma unroll
    for (int s = 0; s < 4; s++) {
        float hv = fmaxf(upv[s] + base, 0.f);
        float v = (lane < 16) ? hv * w2v : 0.f;
#pragma unroll
        for (int o = 16; o > 0; o >>= 1)
            v += __shfl_xor_sync(0xffffffffu, v, o);
        lg[s] = v + ab2v;
    }

    // ---- softmax (fast exp; argmax on logits -> rounding-immune) ----
    float mx = fmaxf(fmaxf(lg[0], lg[1]), fmaxf(lg[2], lg[3]));
    float ew[4], ssum = 0.f;
#pragma unroll
    for (int s = 0; s < 4; s++) { ew[s] = __expf(lg[s] - mx); ssum += ew[s]; }
    float inv = 1.f / ssum;
    float at[4];
#pragma unroll
    for (int s = 0; s < 4; s++) at[s] = ew[s] * inv;

    if (lane < 4) out[B_ + b * 4 + lane] = at[lane];   // at_wt output

    // first-index argmax (strict >) on logits == argmax on at_wt (monotone)
    int mi = 0; float blg = lg[0], bat = at[0];
#pragma unroll
    for (int s = 1; s < 4; s++)
        if (lg[s] > blg) { blg = lg[s]; mi = s; bat = at[s]; }

    // classifier on max-weight member (argmax over 2, tie -> class 0)
    float s0 = fmaf(bat, cw[0], cb[0]);
    float s1 = fmaf(bat, cw[1], cb[1]);
    int pc = (s1 > s0) ? 1 : 0;
    if (lane == 0) out[5 * B_ + b] = (float)pc;        // pred_class output

    float wsv[4];
#pragma unroll
    for (int s = 0; s < 4; s++)
        wsv[s] = pc ? ((s == mi) ? 1.f : 0.f) : at[s];

    // ---- g = group_emb + (leader | weighted member sum) ----
    float gv[8] = {gA.x, gA.y, gA.z, gA.w, gB.x, gB.y, gB.z, gB.w};
    float iv[8] = {iA.x, iA.y, iA.z, iA.w, iB.x, iB.y, iB.z, iB.w};
#pragma unroll
    for (int s = 0; s < 4; s++) {
        float ww = wsv[s];
        gv[0] = fmaf(ww, mA[s].x, gv[0]); gv[1] = fmaf(ww, mA[s].y, gv[1]);
        gv[2] = fmaf(ww, mA[s].z, gv[2]); gv[3] = fmaf(ww, mA[s].w, gv[3]);
        gv[4] = fmaf(ww, mB[s].x, gv[4]); gv[5] = fmaf(ww, mB[s].y, gv[5]);
        gv[6] = fmaf(ww, mB[s].z, gv[6]); gv[7] = fmaf(ww, mB[s].w, gv[7]);
    }

    // ---- prediction MLP: acc[j] += (g*i)*Wa[d][j] + g*Wb[d][j] ----
    float acc[8];
#pragma unroll
    for (int j = 0; j < 8; j++) acc[j] = 0.f;
#pragma unroll
    for (int k = 0; k < 8; k++) {
        float g1 = gv[k];
        float u1 = g1 * iv[k];
        int wbase = (k * 32 + lane) * 2;
#pragma unroll
        for (int j = 0; j < 8; j++) {
            float2 wv = *(const float2*)&Wab[j * 512 + wbase];
            acc[j] = fmaf(u1, wv.x, fmaf(g1, wv.y, acc[j]));
        }
    }
#pragma unroll
    for (int j = 0; j < 8; j++) {
        float v = acc[j];
#pragma unroll
        for (int o = 16; o > 0; o >>= 1)
            v += __shfl_xor_sync(0xffffffffu, v, o);
        acc[j] = v;
    }

    float4 ip0 = *(const float4*)&g_ip[iid * 8];
    float4 ip1 = *(const float4*)&g_ip[iid * 8 + 4];
    float4 b1a = *(const float4*)&pb1[0];
    float4 b1b = *(const float4*)&pb1[4];
    float4 w2a = *(const float4*)&pw2[0];
    float4 w2b = *(const float4*)&pw2[4];
    float ipv[8] = {ip0.x, ip0.y, ip0.z, ip0.w, ip1.x, ip1.y, ip1.z, ip1.w};
    float bv[8]  = {b1a.x, b1a.y, b1a.z, b1a.w, b1b.x, b1b.y, b1b.z, b1b.w};
    float wv2[8] = {w2a.x, w2a.y, w2a.z, w2a.w, w2b.x, w2b.y, w2b.z, w2b.w};

    float z = 0.f;
#pragma unroll
    for (int j = 0; j < 8; j++) {
        float hid = fmaxf(acc[j] + ipv[j] + bv[j], 0.f);
        z = fmaf(hid, wv2[j], z);
    }
    float y = 1.f / (1.f + __expf(-(z + pb2[0])));
    if (lane == 0) out[b] = y;                         // y output
}

// ---------------------------------------------------------------------------
extern "C" void kernel_launch(void* const* d_in, const int* in_sizes, int n_in,
                              void* d_out, int out_size) {
    const int*   gidx = (const int*)d_in[0];
    const int*   iidx = (const int*)d_in[1];
    const int*   gmem = (const int*)d_in[2];
    const float* ue   = (const float*)d_in[3];
    const float* ie   = (const float*)d_in[4];
    const float* ge   = (const float*)d_in[5];
    const float* aw1  = (const float*)d_in[6];
    const float* ab1  = (const float*)d_in[7];
    const float* aw2  = (const float*)d_in[8];
    const float* ab2  = (const float*)d_in[9];
    const float* cw   = (const float*)d_in[10];
    const float* cb   = (const float*)d_in[11];
    const float* pw1  = (const float*)d_in[12];
    const float* pb1  = (const float*)d_in[13];
    const float* pw2  = (const float*)d_in[14];
    const float* pb2  = (const float*)d_in[15];
    float* out = (float*)d_out;

    pre_all<<<1173, 256>>>(ue, ie, aw1, pw1);   // 9375 warp tiles + wab block
    agree_main<<<B_ / 8, 256>>>(gidx, iidx, gmem, ue, ie, ge,
                                ab1, aw2, ab2, cw, cb,
                                pb1, pw2, pb2, out);
}

// round 7
// speedup vs baseline: 1.0040x; 1.0040x over previous
#include <cuda_runtime.h>
#include <math.h>

#define NU_ 200000
#define NI_ 100000
#define NG_ 50000
#define B_  65536
#define D_  256

typedef unsigned long long ull;

// Scratch (static device globals -- no allocation APIs).
__device__ __align__(16) float g_up[NU_ * 16];   // user attention partials
__device__ __align__(16) float g_ia[NI_ * 16];   // item attention partials
__device__ __align__(16) float g_ip[NI_ * 8];    // item prediction partials
__device__ __align__(16) float g_wab[4096];      // permuted pred-MLP weights

// packed f32x2 helpers
__device__ __forceinline__ ull splat2(float x) {
    ull r;
    asm("mov.b64 %0, {%1, %1};" : "=l"(r) : "f"(x));
    return r;
}
__device__ __forceinline__ void fma2(ull& acc, ull a, ull b) {
    asm("fma.rn.f32x2 %0, %1, %2, %0;" : "+l"(acc) : "l"(a), "l"(b));
}

// ---------------------------------------------------------------------------
// Fused precompute. Blocks [0,1172): one warp = one 32-row tile.
//   warps [0,6250): users (16 att outputs)     -> g_up
//   warps [6250,9375): items (16 att + 8 pred) -> g_ia, g_ip
// Block 1172: builds g_wab (permuted pred weights for agree_main).
// Inner product uses packed fma.rn.f32x2 over f-pairs: weight pair is a
// native 64-bit smem load, x is splat once per (row,d). Halves FFMA count.
// ---------------------------------------------------------------------------
__global__ __launch_bounds__(256) void pre_all(const float* __restrict__ ue,
                                               const float* __restrict__ ie,
                                               const float* __restrict__ aw1,
                                               const float* __restrict__ pw1) {
    if (blockIdx.x == 1172) {
        // g_wab[j*512 + (k*32+lane)*2 + {0,1}] = {pw1[d][j], pw1[256+d][j]}
        // with d = (k<4) ? lane*4+k : 128 + lane*4 + (k-4)
        for (int t = 0; t < 16; t++) {
            int idx = t * 256 + threadIdx.x;
            int j = idx >> 9;
            int w = (idx >> 1) & 255;
            int c = idx & 1;
            int k = w >> 5, lane = w & 31;
            int d = (k < 4) ? (lane * 4 + k) : (128 + lane * 4 + (k - 4));
            g_wab[idx] = c ? pw1[(256 + d) * 8 + j] : pw1[d * 8 + j];
        }
        return;
    }

    __shared__ __align__(16) float Wu[256 * 16];
    __shared__ __align__(16) float Wi[256 * 24];
    for (int idx = threadIdx.x; idx < 256 * 16; idx += 256) Wu[idx] = aw1[idx];
    for (int idx = threadIdx.x; idx < 256 * 24; idx += 256) {
        int d = idx / 24, f = idx % 24;
        Wi[idx] = (f < 16) ? aw1[(256 + d) * 16 + f]
                           : pw1[(512 + d) * 8 + (f - 16)];
    }
    __syncthreads();

    int w = blockIdx.x * 8 + (threadIdx.x >> 5);
    if (w >= 9375) return;
    int lane = threadIdx.x & 31;
    int ug = lane >> 2, fg = lane & 3;

    if (w < 6250) {
        // ---- user tile: 32 users x 16 f; lane: 4 users x 2 f-pairs ----
        int u0 = w * 32 + ug * 4;
        const float* r0 = ue + (size_t)u0 * D_;

        ull acc2[4][2];
#pragma unroll
        for (int i = 0; i < 4; i++) { acc2[i][0] = 0ull; acc2[i][1] = 0ull; }

        float4 x[4];
#pragma unroll
        for (int i = 0; i < 4; i++) x[i] = *(const float4*)(r0 + i * D_);

#pragma unroll 2
        for (int q = 0; q < 64; q++) {
            float4 xn[4];
            if (q < 63) {
#pragma unroll
                for (int i = 0; i < 4; i++)
                    xn[i] = *(const float4*)(r0 + i * D_ + (q + 1) * 4);
            }
#pragma unroll
            for (int dd = 0; dd < 4; dd++) {
                ulonglong2 bp =
                    *(const ulonglong2*)&Wu[(q * 4 + dd) * 16 + fg * 4];
#pragma unroll
                for (int i = 0; i < 4; i++) {
                    float xv = (dd == 0) ? x[i].x : (dd == 1) ? x[i].y
                              : (dd == 2) ? x[i].z : x[i].w;
                    ull xs = splat2(xv);
                    fma2(acc2[i][0], xs, bp.x);
                    fma2(acc2[i][1], xs, bp.y);
                }
            }
            if (q < 63) {
#pragma unroll
                for (int i = 0; i < 4; i++) x[i] = xn[i];
            }
        }
#pragma unroll
        for (int i = 0; i < 4; i++) {
            *(ull*)&g_up[(u0 + i) * 16 + fg * 4 + 0] = acc2[i][0];
            *(ull*)&g_up[(u0 + i) * 16 + fg * 4 + 2] = acc2[i][1];
        }
    } else {
        // ---- item tile: 32 items x 24 f; lane: 4 items x 3 f-pairs ----
        int t = w - 6250;
        int i0 = t * 32 + ug * 4;
        const float* r0 = ie + (size_t)i0 * D_;

        ull acc2[4][3];
#pragma unroll
        for (int i = 0; i < 4; i++)
#pragma unroll
            for (int p = 0; p < 3; p++) acc2[i][p] = 0ull;

        float4 x[4];
#pragma unroll
        for (int i = 0; i < 4; i++) x[i] = *(const float4*)(r0 + i * D_);

#pragma unroll 2
        for (int q = 0; q < 64; q++) {
            float4 xn[4];
            if (q < 63) {
#pragma unroll
                for (int i = 0; i < 4; i++)
                    xn[i] = *(const float4*)(r0 + i * D_ + (q + 1) * 4);
            }
#pragma unroll
            for (int dd = 0; dd < 4; dd++) {
                const float* wr = &Wi[(q * 4 + dd) * 24 + fg * 6];
                ull b0 = *(const ull*)(wr + 0);
                ull b1 = *(const ull*)(wr + 2);
                ull b2 = *(const ull*)(wr + 4);
#pragma unroll
                for (int i = 0; i < 4; i++) {
                    float xv = (dd == 0) ? x[i].x : (dd == 1) ? x[i].y
                              : (dd == 2) ? x[i].z : x[i].w;
                    ull xs = splat2(xv);
                    fma2(acc2[i][0], xs, b0);
                    fma2(acc2[i][1], xs, b1);
                    fma2(acc2[i][2], xs, b2);
                }
            }
            if (q < 63) {
#pragma unroll
                for (int i = 0; i < 4; i++) x[i] = xn[i];
            }
        }
#pragma unroll
        for (int i = 0; i < 4; i++)
#pragma unroll
            for (int p = 0; p < 3; p++) {
                int f = fg * 6 + 2 * p;      // even; pair never straddles f=16
                int it = i0 + i;
                if (f < 16) *(ull*)&g_ia[it * 16 + f] = acc2[i][p];
                else        *(ull*)&g_ip[it * 8 + (f - 16)] = acc2[i][p];
            }
    }
}

// ---------------------------------------------------------------------------
// Main kernel: one warp per batch element, 8 warps/block.
// Lane owns d in {lane*4+r} U {128+lane*4+r}: fully-coalesced LDG.128 rows.
// ALL loads (12 heavy rows + 5 attention-partial rows) issued before any
// dependent math so DRAM/L2 latency hides under the scalar section.
// ---------------------------------------------------------------------------
__global__ __launch_bounds__(256) void agree_main(
    const int*   __restrict__ gidx, const int*   __restrict__ iidx,
    const int*   __restrict__ gmem, const float* __restrict__ ue,
    const float* __restrict__ ie,   const float* __restrict__ ge,
    const float* __restrict__ ab1,  const float* __restrict__ aw2,
    const float* __restrict__ ab2,  const float* __restrict__ cw,
    const float* __restrict__ cb,   const float* __restrict__ pb1,
    const float* __restrict__ pw2,  const float* __restrict__ pb2,
    float* __restrict__ out) {
    __shared__ __align__(16) float Wab[4096];
    {
        const float4* s4 = (const float4*)g_wab;
        float4* d4 = (float4*)Wab;
#pragma unroll
        for (int i = 0; i < 4; i++)
            d4[threadIdx.x + i * 256] = s4[threadIdx.x + i * 256];
    }
    __syncthreads();

    int b = blockIdx.x * 8 + (threadIdx.x >> 5);
    int lane = threadIdx.x & 31;
    int f = lane & 15;

    int gid = gidx[b];
    int iid = iidx[b];
    int4 mv = ((const int4*)gmem)[gid];
    int m[4] = {mv.x, mv.y, mv.z, mv.w};

    // ---- issue every load up front ----
    const float* gr = ge + (size_t)gid * D_;
    const float* ir = ie + (size_t)iid * D_;
    float4 gA = *(const float4*)(gr + lane * 4);
    float4 gB = *(const float4*)(gr + 128 + lane * 4);
    float4 iA = *(const float4*)(ir + lane * 4);
    float4 iB = *(const float4*)(ir + 128 + lane * 4);
    float iav = g_ia[iid * 16 + f];
    float upv[4];
    float4 mA[4], mB[4];
#pragma unroll
    for (int s = 0; s < 4; s++) {
        const float* mr = ue + (size_t)m[s] * D_;
        mA[s] = *(const float4*)(mr + lane * 4);
        mB[s] = *(const float4*)(mr + 128 + lane * 4);
        upv[s] = g_up[m[s] * 16 + f];
    }

    // ---- attention logits from precomputed partials ----
    float base = iav + ab1[f];
    float w2v = aw2[f];
    float ab2v = ab2[0];
    float lg[4];
#pragma unroll
    for (int s = 0; s < 4; s++) {
        float hv = fmaxf(upv[s] + base, 0.f);
        float v = (lane < 16) ? hv * w2v : 0.f;
#pragma unroll
        for (int o = 16; o > 0; o >>= 1)
            v += __shfl_xor_sync(0xffffffffu, v, o);
        lg[s] = v + ab2v;
    }

    // ---- softmax (fast exp; argmax on logits -> rounding-immune) ----
    float mx = fmaxf(fmaxf(lg[0], lg[1]), fmaxf(lg[2], lg[3]));
    float ew[4], ssum = 0.f;
#pragma unroll
    for (int s = 0; s < 4; s++) { ew[s] = __expf(lg[s] - mx); ssum += ew[s]; }
    float inv = 1.f / ssum;
    float at[4];
#pragma unroll
    for (int s = 0; s < 4; s++) at[s] = ew[s] * inv;

    if (lane < 4) out[B_ + b * 4 + lane] = at[lane];   // at_wt output

    // first-index argmax (strict >) on logits == argmax on at_wt (monotone)
    int mi = 0; float blg = lg[0], bat = at[0];
#pragma unroll
    for (int s = 1; s < 4; s++)
        if (lg[s] > blg) { blg = lg[s]; mi = s; bat = at[s]; }

    // classifier on max-weight member (argmax over 2, tie -> class 0)
    float s0 = fmaf(bat, cw[0], cb[0]);
    float s1 = fmaf(bat, cw[1], cb[1]);
    int pc = (s1 > s0) ? 1 : 0;
    if (lane == 0) out[5 * B_ + b] = (float)pc;        // pred_class output

    float wsv[4];
#pragma unroll
    for (int s = 0; s < 4; s++)
        wsv[s] = pc ? ((s == mi) ? 1.f : 0.f) : at[s];

    // ---- g = group_emb + (leader | weighted member sum) ----
    float gv[8] = {gA.x, gA.y, gA.z, gA.w, gB.x, gB.y, gB.z, gB.w};
    float iv[8] = {iA.x, iA.y, iA.z, iA.w, iB.x, iB.y, iB.z, iB.w};
#pragma unroll
    for (int s = 0; s < 4; s++) {
        float ww = wsv[s];
        gv[0] = fmaf(ww, mA[s].x, gv[0]); gv[1] = fmaf(ww, mA[s].y, gv[1]);
        gv[2] = fmaf(ww, mA[s].z, gv[2]); gv[3] = fmaf(ww, mA[s].w, gv[3]);
        gv[4] = fmaf(ww, mB[s].x, gv[4]); gv[5] = fmaf(ww, mB[s].y, gv[5]);
        gv[6] = fmaf(ww, mB[s].z, gv[6]); gv[7] = fmaf(ww, mB[s].w, gv[7]);
    }

    // ---- prediction MLP: acc[j] += (g*i)*Wa[d][j] + g*Wb[d][j] ----
    float acc[8];
#pragma unroll
    for (int j = 0; j < 8; j++) acc[j] = 0.f;
#pragma unroll
    for (int k = 0; k < 8; k++) {
        float g1 = gv[k];
        float u1 = g1 * iv[k];
        int wbase = (k * 32 + lane) * 2;
#pragma unroll
        for (int j = 0; j < 8; j++) {
            float2 wv = *(const float2*)&Wab[j * 512 + wbase];
            acc[j] = fmaf(u1, wv.x, fmaf(g1, wv.y, acc[j]));
        }
    }
#pragma unroll
    for (int j = 0; j < 8; j++) {
        float v = acc[j];
#pragma unroll
        for (int o = 16; o > 0; o >>= 1)
            v += __shfl_xor_sync(0xffffffffu, v, o);
        acc[j] = v;
    }

    float4 ip0 = *(const float4*)&g_ip[iid * 8];
    float4 ip1 = *(const float4*)&g_ip[iid * 8 + 4];
    float4 b1a = *(const float4*)&pb1[0];
    float4 b1b = *(const float4*)&pb1[4];
    float4 w2a = *(const float4*)&pw2[0];
    float4 w2b = *(const float4*)&pw2[4];
    float ipv[8] = {ip0.x, ip0.y, ip0.z, ip0.w, ip1.x, ip1.y, ip1.z, ip1.w};
    float bv[8]  = {b1a.x, b1a.y, b1a.z, b1a.w, b1b.x, b1b.y, b1b.z, b1b.w};
    float wv2[8] = {w2a.x, w2a.y, w2a.z, w2a.w, w2b.x, w2b.y, w2b.z, w2b.w};

    float z = 0.f;
#pragma unroll
    for (int j = 0; j < 8; j++) {
        float hid = fmaxf(acc[j] + ipv[j] + bv[j], 0.f);
        z = fmaf(hid, wv2[j], z);
    }
    float y = 1.f / (1.f + __expf(-(z + pb2[0])));
    if (lane == 0) out[b] = y;                         // y output
}

// ---------------------------------------------------------------------------
extern "C" void kernel_launch(void* const* d_in, const int* in_sizes, int n_in,
                              void* d_out, int out_size) {
    const int*   gidx = (const int*)d_in[0];
    const int*   iidx = (const int*)d_in[1];
    const int*   gmem = (const int*)d_in[2];
    const float* ue   = (const float*)d_in[3];
    const float* ie   = (const float*)d_in[4];
    const float* ge   = (const float*)d_in[5];
    const float* aw1  = (const float*)d_in[6];
    const float* ab1  = (const float*)d_in[7];
    const float* aw2  = (const float*)d_in[8];
    const float* ab2  = (const float*)d_in[9];
    const float* cw   = (const float*)d_in[10];
    const float* cb   = (const float*)d_in[11];
    const float* pw1  = (const float*)d_in[12];
    const float* pb1  = (const float*)d_in[13];
    const float* pw2  = (const float*)d_in[14];
    const float* pb2  = (const float*)d_in[15];
    float* out = (float*)d_out;

    pre_all<<<1173, 256>>>(ue, ie, aw1, pw1);   // 9375 warp tiles + wab block
    agree_main<<<B_ / 8, 256>>>(gidx, iidx, gmem, ue, ie, ge,
                                ab1, aw2, ab2, cw, cb,
                                pb1, pw2, pb2, out);
}